// round 15
// baseline (speedup 1.0000x reference)
#include <cuda_runtime.h>
#include <math.h>
#include <stdint.h>

// Problem constants
#define BB   2
#define SS   2048
#define DM   1024
#define NH   16
#define HDIM 64

#define XN (BB * SS * DM)    // 4M
#define WN (DM * DM)         // 1M

// Scratch (device globals: allocation-free)
__device__ uint32_t g_qt[XN];                    // Q proj (tf32, pre-scaled)
__device__ uint32_t g_kt[XN];                    // K proj (tf32)
__device__ uint32_t g_vt[BB * NH * HDIM * SS];   // V^T (tf32)
// pre-converted operands
__device__ uint32_t g_xq[XN], g_xk[XN], g_xv[XN];
__device__ uint32_t g_wq[WN], g_wk[WN], g_wvh[WN], g_wvl[WN];

// ---------------------------------------------------------------------------
// Helpers
// ---------------------------------------------------------------------------
__device__ __forceinline__ uint32_t cvt_tf32(float x) {
    uint32_t u;
    asm("cvt.rna.tf32.f32 %0, %1;" : "=r"(u) : "f"(x));
    return u;
}

__device__ __forceinline__ void mma_tf32(float* c,
                                         uint32_t a0, uint32_t a1, uint32_t a2, uint32_t a3,
                                         uint32_t b0, uint32_t b1) {
    asm volatile(
        "mma.sync.aligned.m16n8k8.row.col.f32.tf32.tf32.f32 "
        "{%0,%1,%2,%3}, {%4,%5,%6,%7}, {%8,%9}, {%0,%1,%2,%3};\n"
        : "+f"(c[0]), "+f"(c[1]), "+f"(c[2]), "+f"(c[3])
        : "r"(a0), "r"(a1), "r"(a2), "r"(a3), "r"(b0), "r"(b1));
}

__device__ __forceinline__ void cp_async16(void* smem, const void* gmem) {
    uint32_t s = (uint32_t)__cvta_generic_to_shared(smem);
    asm volatile("cp.async.ca.shared.global [%0], [%1], 16;\n" :: "r"(s), "l"(gmem));
}
__device__ __forceinline__ void cp_commit() {
    asm volatile("cp.async.commit_group;\n");
}
__device__ __forceinline__ void cp_wait1() {
    asm volatile("cp.async.wait_group 1;\n");
}
__device__ __forceinline__ void cp_wait0() {
    asm volatile("cp.async.wait_group 0;\n");
}

// ---------------------------------------------------------------------------
// Prepass: elementwise fp32 -> tf32 (and split for Wv)
// ---------------------------------------------------------------------------
__global__ __launch_bounds__(256) void cvt_arr(const float* __restrict__ in,
                                               uint32_t* __restrict__ out, int n4)
{
    int i = blockIdx.x * 256 + threadIdx.x;
    if (i >= n4) return;
    float4 v = *(const float4*)&in[i * 4];
    uint4 o;
    o.x = cvt_tf32(v.x); o.y = cvt_tf32(v.y);
    o.z = cvt_tf32(v.z); o.w = cvt_tf32(v.w);
    *(uint4*)&out[i * 4] = o;
}

__global__ __launch_bounds__(256) void split_arr(const float* __restrict__ in,
                                                 uint32_t* __restrict__ hi,
                                                 uint32_t* __restrict__ lo, int n4)
{
    int i = blockIdx.x * 256 + threadIdx.x;
    if (i >= n4) return;
    float4 v = *(const float4*)&in[i * 4];
    uint4 h, l;
    float f[4] = {v.x, v.y, v.z, v.w};
    uint32_t hh[4], ll[4];
#pragma unroll
    for (int k = 0; k < 4; k++) {
        hh[k] = __float_as_uint(f[k]) & 0xFFFFE000u;           // tf32-exact hi
        ll[k] = cvt_tf32(f[k] - __uint_as_float(hh[k]));       // rounded residual
    }
    h.x = hh[0]; h.y = hh[1]; h.z = hh[2]; h.w = hh[3];
    l.x = ll[0]; l.y = ll[1]; l.z = ll[2]; l.w = ll[3];
    *(uint4*)&hi[i * 4] = h;
    *(uint4*)&lo[i * 4] = l;
}

// ---------------------------------------------------------------------------
// Fused projection GEMMs on pre-converted tf32 operands. blockIdx.z = mode.
// CTA tile 128x64, BK=16, 256 threads, warp 32x32, 3-stage cp.async pipeline.
//  z=0: Q (1-pass, out *1/32)   z=1: K (1-pass)   z=2: V (2-pass, W-side exact)
// ---------------------------------------------------------------------------
#define BM 128
#define BN 64
#define BK 16
#define KPAD 4
#define BKP (BK + KPAD)
#define NSTG 3

__device__ __forceinline__ void gemm_load_stage(
    const uint32_t* __restrict__ X, const uint32_t* __restrict__ W0,
    const uint32_t* __restrict__ W1,
    uint32_t (*As)[BKP], uint32_t (*Bs0)[BKP], uint32_t (*Bs1)[BKP],
    int m0, int n0, int k0, int mode, int tid)
{
#pragma unroll
    for (int i = 0; i < 2; i++) {
        int f   = tid + i * 256;
        int row = f >> 2;
        int kq  = (f & 3) * 4;
        cp_async16(&As[row][kq], &X[(size_t)(m0 + row) * DM + k0 + kq]);
    }
    {
        int row = tid >> 2;
        int kq  = (tid & 3) * 4;
        cp_async16(&Bs0[row][kq], &W0[(size_t)(n0 + row) * DM + k0 + kq]);
        if (mode == 2)
            cp_async16(&Bs1[row][kq], &W1[(size_t)(n0 + row) * DM + k0 + kq]);
    }
    cp_commit();
}

__global__ __launch_bounds__(256) void gemm_fused(
    const float* __restrict__ bq, const float* __restrict__ bk,
    const float* __restrict__ bv,
    uint32_t* __restrict__ YQ, uint32_t* __restrict__ YK,
    uint32_t* __restrict__ VT)
{
    __shared__ __align__(16) uint32_t As[NSTG][BM][BKP];
    __shared__ __align__(16) uint32_t Bs0[NSTG][BN][BKP];
    __shared__ __align__(16) uint32_t Bs1[NSTG][BN][BKP];

    const int mode = blockIdx.z;
    const uint32_t* X  = (mode == 0) ? g_xq : (mode == 1) ? g_xk : g_xv;
    const uint32_t* W0 = (mode == 0) ? g_wq : (mode == 1) ? g_wk : g_wvh;
    const uint32_t* W1 = g_wvl;
    const float* bias  = (mode == 0) ? bq : (mode == 1) ? bk : bv;

    const int tid  = threadIdx.x;
    const int warp = tid >> 5;
    const int lane = tid & 31;
    const int wm = (warp >> 1) * 32;
    const int wn = (warp & 1) * 32;
    const int g  = lane >> 2;
    const int tg = lane & 3;
    const int m0 = blockIdx.y * BM;
    const int n0 = blockIdx.x * BN;
    const int NIT = DM / BK;

    float c[2][4][4];
#pragma unroll
    for (int mt = 0; mt < 2; mt++)
#pragma unroll
        for (int nt = 0; nt < 4; nt++)
#pragma unroll
            for (int r = 0; r < 4; r++) c[mt][nt][r] = 0.0f;

    gemm_load_stage(X, W0, W1, As[0], Bs0[0], Bs1[0], m0, n0, 0, mode, tid);
    gemm_load_stage(X, W0, W1, As[1], Bs0[1], Bs1[1], m0, n0, BK, mode, tid);

    for (int it = 0; it < NIT; it++) {
        if (it + 2 < NIT) cp_wait1(); else cp_wait0();
        __syncthreads();
        if (it + 2 < NIT)
            gemm_load_stage(X, W0, W1, As[(it + 2) % NSTG], Bs0[(it + 2) % NSTG],
                            Bs1[(it + 2) % NSTG], m0, n0, (it + 2) * BK, mode, tid);

        const int st = it % NSTG;
#pragma unroll
        for (int ks = 0; ks < 2; ks++) {
            const int kb = ks * 8;
            uint32_t a[2][4];
#pragma unroll
            for (int mt = 0; mt < 2; mt++) {
                int r0 = wm + mt * 16;
                a[mt][0] = As[st][r0 + g    ][kb + tg    ];
                a[mt][1] = As[st][r0 + g + 8][kb + tg    ];
                a[mt][2] = As[st][r0 + g    ][kb + tg + 4];
                a[mt][3] = As[st][r0 + g + 8][kb + tg + 4];
            }
#pragma unroll
            for (int nt = 0; nt < 4; nt++) {
                int nr = wn + nt * 8 + g;
                uint32_t b0 = Bs0[st][nr][kb + tg    ];
                uint32_t b1 = Bs0[st][nr][kb + tg + 4];
#pragma unroll
                for (int mt = 0; mt < 2; mt++)
                    mma_tf32(c[mt][nt], a[mt][0], a[mt][1], a[mt][2], a[mt][3], b0, b1);
                if (mode == 2) {
                    uint32_t l0 = Bs1[st][nr][kb + tg    ];
                    uint32_t l1 = Bs1[st][nr][kb + tg + 4];
#pragma unroll
                    for (int mt = 0; mt < 2; mt++)
                        mma_tf32(c[mt][nt], a[mt][0], a[mt][1], a[mt][2], a[mt][3], l0, l1);
                }
            }
        }
        __syncthreads();
    }

    if (mode < 2) {
        uint32_t* Y = (mode == 0) ? YQ : YK;
        const float oscale = (mode == 0) ? 0.03125f : 1.0f;
#pragma unroll
        for (int mt = 0; mt < 2; mt++) {
#pragma unroll
            for (int nt = 0; nt < 4; nt++) {
                int m = m0 + wm + mt * 16 + g;
                int n = n0 + wn + nt * 8 + tg * 2;
                float b0 = bias[n];
                float b1 = bias[n + 1];
                Y[(size_t)m * DM + n]           = cvt_tf32((c[mt][nt][0] + b0) * oscale);
                Y[(size_t)m * DM + n + 1]       = cvt_tf32((c[mt][nt][1] + b1) * oscale);
                Y[(size_t)(m + 8) * DM + n]     = cvt_tf32((c[mt][nt][2] + b0) * oscale);
                Y[(size_t)(m + 8) * DM + n + 1] = cvt_tf32((c[mt][nt][3] + b1) * oscale);
            }
        }
    } else {
        // Transposed epilogue: m=(b,s), n=(h,d) -> VT[((b*NH+h)*HDIM+d)*SS + s], tf32
#pragma unroll
        for (int mt = 0; mt < 2; mt++) {
#pragma unroll
            for (int nt = 0; nt < 4; nt++) {
                int m = m0 + wm + mt * 16 + g;
                int n = n0 + wn + nt * 8 + tg * 2;
                int bidx = m >> 11, s = m & 2047;
#pragma unroll
                for (int e = 0; e < 2; e++) {
                    int nn = n + e;
                    int hh = nn >> 6, dd = nn & 63;
                    size_t base = (((size_t)(bidx * NH + hh)) * HDIM + dd) * SS;
                    float bb = bias[nn];
                    VT[base + s]     = cvt_tf32(c[mt][nt][e]     + bb);
                    VT[base + s + 8] = cvt_tf32(c[mt][nt][e + 2] + bb);
                }
            }
        }
    }
}

// ---------------------------------------------------------------------------
// Tensor-core flash attention (TF32), causal. 128 threads, 4 warps x 32 q-rows.
// cp.async double-buffered K/V tiles: prefetch kt+1 while computing kt.
// ---------------------------------------------------------------------------
#define QT 128
#define KT 64
#define PSTR 68
#define TILE_U32 (64 * PSTR)
#define FA_SMEM ((4 * TILE_U32 + 4 * 32 * PSTR) * (int)sizeof(uint32_t))

__global__ __launch_bounds__(128) void flash_attn_tc(
    const uint32_t* __restrict__ Qt, const uint32_t* __restrict__ Kt,
    const uint32_t* __restrict__ VT, float* __restrict__ O)
{
    extern __shared__ uint32_t smu[];
    // buffers: sK[0], sK[1], sV[0], sV[1], then per-warp P
    uint32_t* sKb[2] = { smu, smu + TILE_U32 };
    uint32_t* sVb[2] = { smu + 2 * TILE_U32, smu + 3 * TILE_U32 };
    uint32_t* sP = smu + 4 * TILE_U32;

    const int tid  = threadIdx.x;
    const int w    = tid >> 5;
    const int lane = tid & 31;
    const int g    = lane >> 2;
    const int tg   = lane & 3;
    const int qt   = (int)gridDim.x - 1 - (int)blockIdx.x;
    const int h    = blockIdx.y;
    const int b    = blockIdx.z;
    const int qbase = qt * QT;
    const float NEG = -1.0e30f;

    const uint32_t* Qg = Qt + ((size_t)(b * SS) + qbase) * DM + h * HDIM;
    const uint32_t* Kbase = Kt + (size_t)(b * SS) * DM + h * HDIM;
    const size_t vrow = ((size_t)(b * NH + h) * HDIM) * SS;

    uint32_t qf[2][8][4];
#pragma unroll
    for (int mt = 0; mt < 2; mt++) {
        int r0 = w * 32 + mt * 16 + g;
#pragma unroll
        for (int ks = 0; ks < 8; ks++) {
            int cc = ks * 8 + tg;
            qf[mt][ks][0] = Qg[(size_t)(r0    ) * DM + cc    ];
            qf[mt][ks][1] = Qg[(size_t)(r0 + 8) * DM + cc    ];
            qf[mt][ks][2] = Qg[(size_t)(r0    ) * DM + cc + 4];
            qf[mt][ks][3] = Qg[(size_t)(r0 + 8) * DM + cc + 4];
        }
    }

    float of[2][8][4];
    float mrow[2][2], lrow[2][2];
#pragma unroll
    for (int mt = 0; mt < 2; mt++) {
        mrow[mt][0] = NEG; mrow[mt][1] = NEG;
        lrow[mt][0] = 0.f; lrow[mt][1] = 0.f;
#pragma unroll
        for (int nt = 0; nt < 8; nt++)
#pragma unroll
            for (int r = 0; r < 4; r++) of[mt][nt][r] = 0.f;
    }

    uint32_t* Pw = sP + w * 32 * PSTR;
    const int nkt = 2 * qt + 2;
    const int ldrow = tid >> 4;            // 0..7
    const int ldc4  = (tid & 15) * 4;

    // prefetch tile 0
#pragma unroll
    for (int i = 0; i < 8; i++) {
        int row = ldrow + i * 8;
        cp_async16(&sKb[0][row * PSTR + ldc4], &Kbase[(size_t)row * DM + ldc4]);
        cp_async16(&sVb[0][row * PSTR + ldc4], &VT[vrow + (size_t)row * SS + ldc4]);
    }
    cp_commit();

    for (int kt = 0; kt < nkt; kt++) {
        cp_wait0();
        __syncthreads();
        if (kt + 1 < nkt) {
            const int nb = (kt + 1) & 1;
            const uint32_t* Kg = Kbase + (size_t)((kt + 1) * KT) * DM;
            const size_t vb = vrow + (kt + 1) * KT;
#pragma unroll
            for (int i = 0; i < 8; i++) {
                int row = ldrow + i * 8;
                cp_async16(&sKb[nb][row * PSTR + ldc4], &Kg[(size_t)row * DM + ldc4]);
                cp_async16(&sVb[nb][row * PSTR + ldc4], &VT[vb + (size_t)row * SS + ldc4]);
            }
            cp_commit();
        }

        if (kt * KT > qbase + w * 32 + 31) continue;   // masked for this warp
        const uint32_t* sK = sKb[kt & 1];
        const uint32_t* sV = sVb[kt & 1];

        float s[2][8][4];
#pragma unroll
        for (int mt = 0; mt < 2; mt++)
#pragma unroll
            for (int nt = 0; nt < 8; nt++)
#pragma unroll
                for (int r = 0; r < 4; r++) s[mt][nt][r] = 0.f;

#pragma unroll
        for (int ks = 0; ks < 8; ks++) {
#pragma unroll
            for (int nt = 0; nt < 8; nt++) {
                int nr = nt * 8 + g;
                uint32_t b0 = sK[nr * PSTR + ks * 8 + tg    ];
                uint32_t b1 = sK[nr * PSTR + ks * 8 + tg + 4];
                mma_tf32(s[0][nt], qf[0][ks][0], qf[0][ks][1], qf[0][ks][2], qf[0][ks][3], b0, b1);
                mma_tf32(s[1][nt], qf[1][ks][0], qf[1][ks][1], qf[1][ks][2], qf[1][ks][3], b0, b1);
            }
        }

        if (kt >= 2 * qt) {
#pragma unroll
            for (int mt = 0; mt < 2; mt++) {
                int row0 = qbase + w * 32 + mt * 16 + g;
#pragma unroll
                for (int nt = 0; nt < 8; nt++) {
                    int col = kt * KT + nt * 8 + 2 * tg;
                    if (col     > row0    ) s[mt][nt][0] = NEG;
                    if (col + 1 > row0    ) s[mt][nt][1] = NEG;
                    if (col     > row0 + 8) s[mt][nt][2] = NEG;
                    if (col + 1 > row0 + 8) s[mt][nt][3] = NEG;
                }
            }
        }

#pragma unroll
        for (int mt = 0; mt < 2; mt++) {
            float rm0 = NEG, rm1 = NEG;
#pragma unroll
            for (int nt = 0; nt < 8; nt++) {
                rm0 = fmaxf(rm0, fmaxf(s[mt][nt][0], s[mt][nt][1]));
                rm1 = fmaxf(rm1, fmaxf(s[mt][nt][2], s[mt][nt][3]));
            }
#pragma unroll
            for (int d = 1; d < 4; d <<= 1) {
                rm0 = fmaxf(rm0, __shfl_xor_sync(0xffffffffu, rm0, d));
                rm1 = fmaxf(rm1, __shfl_xor_sync(0xffffffffu, rm1, d));
            }
            float mn0 = fmaxf(mrow[mt][0], rm0);
            float mn1 = fmaxf(mrow[mt][1], rm1);
            float corr0 = __expf(mrow[mt][0] - mn0);
            float corr1 = __expf(mrow[mt][1] - mn1);
            float rs0 = 0.f, rs1 = 0.f;
#pragma unroll
            for (int nt = 0; nt < 8; nt++) {
                s[mt][nt][0] = __expf(s[mt][nt][0] - mn0);
                s[mt][nt][1] = __expf(s[mt][nt][1] - mn0);
                s[mt][nt][2] = __expf(s[mt][nt][2] - mn1);
                s[mt][nt][3] = __expf(s[mt][nt][3] - mn1);
                rs0 += s[mt][nt][0] + s[mt][nt][1];
                rs1 += s[mt][nt][2] + s[mt][nt][3];
            }
#pragma unroll
            for (int d = 1; d < 4; d <<= 1) {
                rs0 += __shfl_xor_sync(0xffffffffu, rs0, d);
                rs1 += __shfl_xor_sync(0xffffffffu, rs1, d);
            }
            lrow[mt][0] = lrow[mt][0] * corr0 + rs0;
            lrow[mt][1] = lrow[mt][1] * corr1 + rs1;
            mrow[mt][0] = mn0;
            mrow[mt][1] = mn1;
#pragma unroll
            for (int nt = 0; nt < 8; nt++) {
                of[mt][nt][0] *= corr0;
                of[mt][nt][1] *= corr0;
                of[mt][nt][2] *= corr1;
                of[mt][nt][3] *= corr1;
            }
            int pr = mt * 16 + g;
#pragma unroll
            for (int nt = 0; nt < 8; nt++) {
                uint2 p01 = make_uint2(cvt_tf32(s[mt][nt][0]), cvt_tf32(s[mt][nt][1]));
                uint2 p23 = make_uint2(cvt_tf32(s[mt][nt][2]), cvt_tf32(s[mt][nt][3]));
                *(uint2*)&Pw[(pr    ) * PSTR + nt * 8 + 2 * tg] = p01;
                *(uint2*)&Pw[(pr + 8) * PSTR + nt * 8 + 2 * tg] = p23;
            }
        }
        __syncwarp();

        // O += P V (single-pass tf32)
#pragma unroll
        for (int ks = 0; ks < 8; ks++) {
            uint32_t a[2][4];
#pragma unroll
            for (int mt = 0; mt < 2; mt++) {
                int pr = mt * 16 + g;
                int cc = ks * 8 + tg;
                a[mt][0] = Pw[(pr    ) * PSTR + cc    ];
                a[mt][1] = Pw[(pr + 8) * PSTR + cc    ];
                a[mt][2] = Pw[(pr    ) * PSTR + cc + 4];
                a[mt][3] = Pw[(pr + 8) * PSTR + cc + 4];
            }
#pragma unroll
            for (int nt = 0; nt < 8; nt++) {
                int nr = nt * 8 + g;
                uint32_t b0 = sV[nr * PSTR + ks * 8 + tg    ];
                uint32_t b1 = sV[nr * PSTR + ks * 8 + tg + 4];
#pragma unroll
                for (int mt = 0; mt < 2; mt++)
                    mma_tf32(of[mt][nt], a[mt][0], a[mt][1], a[mt][2], a[mt][3], b0, b1);
            }
        }
        __syncwarp();
    }

    float* Og = O + ((size_t)(b * SS) + qbase) * DM + h * HDIM;
#pragma unroll
    for (int mt = 0; mt < 2; mt++) {
        float inv0 = 1.0f / lrow[mt][0];
        float inv1 = 1.0f / lrow[mt][1];
        int r0 = w * 32 + mt * 16 + g;
#pragma unroll
        for (int nt = 0; nt < 8; nt++) {
            int cc = nt * 8 + 2 * tg;
            *(float2*)&Og[(size_t)(r0    ) * DM + cc] =
                make_float2(of[mt][nt][0] * inv0, of[mt][nt][1] * inv0);
            *(float2*)&Og[(size_t)(r0 + 8) * DM + cc] =
                make_float2(of[mt][nt][2] * inv1, of[mt][nt][3] * inv1);
        }
    }
}

// ---------------------------------------------------------------------------
// kernel_launch
// ---------------------------------------------------------------------------
extern "C" void kernel_launch(void* const* d_in, const int* in_sizes, int n_in,
                              void* d_out, int out_size)
{
    const float* qx = (const float*)d_in[0];
    const float* kx = (const float*)d_in[1];
    const float* vx = (const float*)d_in[2];
    const float* Wq = (const float*)d_in[4];
    const float* bq = (const float*)d_in[5];
    const float* Wk = (const float*)d_in[6];
    const float* bk = (const float*)d_in[7];
    const float* Wv = (const float*)d_in[8];
    const float* bv = (const float*)d_in[9];
    float* out = (float*)d_out;

    uint32_t *gq, *gk, *gv;
    uint32_t *xq, *xk, *xv, *wq, *wk, *wvh, *wvl;
    cudaGetSymbolAddress((void**)&gq,  g_qt);
    cudaGetSymbolAddress((void**)&gk,  g_kt);
    cudaGetSymbolAddress((void**)&gv,  g_vt);
    cudaGetSymbolAddress((void**)&xq,  g_xq);
    cudaGetSymbolAddress((void**)&xk,  g_xk);
    cudaGetSymbolAddress((void**)&xv,  g_xv);
    cudaGetSymbolAddress((void**)&wq,  g_wq);
    cudaGetSymbolAddress((void**)&wk,  g_wk);
    cudaGetSymbolAddress((void**)&wvh, g_wvh);
    cudaGetSymbolAddress((void**)&wvl, g_wvl);

    // prepass conversions
    cvt_arr<<<XN / 4 / 256, 256>>>(qx, xq, XN / 4);
    cvt_arr<<<XN / 4 / 256, 256>>>(kx, xk, XN / 4);
    cvt_arr<<<XN / 4 / 256, 256>>>(vx, xv, XN / 4);
    cvt_arr<<<WN / 4 / 256, 256>>>(Wq, wq, WN / 4);
    cvt_arr<<<WN / 4 / 256, 256>>>(Wk, wk, WN / 4);
    split_arr<<<WN / 4 / 256, 256>>>(Wv, wvh, wvl, WN / 4);

    dim3 ggrid(DM / BN, (BB * SS) / BM, 3);   // (16, 32, 3)
    gemm_fused<<<ggrid, 256>>>(bq, bk, bv, gq, gk, gv);

    cudaFuncSetAttribute(flash_attn_tc,
                         cudaFuncAttributeMaxDynamicSharedMemorySize, FA_SMEM);
    dim3 agrid(SS / QT, NH, BB);    // (16, 16, 2)
    flash_attn_tc<<<agrid, 128, FA_SMEM>>>(gq, gk, gv, out);
}

// round 16
// speedup vs baseline: 1.3583x; 1.3583x over previous
#include <cuda_runtime.h>
#include <math.h>
#include <stdint.h>

// Problem constants
#define BB   2
#define SS   2048
#define DM   1024
#define NH   16
#define HDIM 64

// Scratch (device globals: allocation-free)
__device__ uint32_t g_qt[BB * SS * DM];
__device__ uint32_t g_kt[BB * SS * DM];
__device__ uint32_t g_vt[BB * NH * HDIM * SS];   // V^T as single tf32 plane

// ---------------------------------------------------------------------------
// Helpers
// ---------------------------------------------------------------------------
__device__ __forceinline__ void tf32_split(float x, uint32_t& hi, uint32_t& lo) {
    uint32_t xh = __float_as_uint(x) & 0xFFFFE000u;
    hi = xh;
    lo = __float_as_uint(x - __uint_as_float(xh));
}

__device__ __forceinline__ uint32_t cvt_tf32(float x) {
    uint32_t u;
    asm("cvt.rna.tf32.f32 %0, %1;" : "=r"(u) : "f"(x));
    return u;
}

__device__ __forceinline__ void mma_tf32(float* c,
                                         uint32_t a0, uint32_t a1, uint32_t a2, uint32_t a3,
                                         uint32_t b0, uint32_t b1) {
    asm volatile(
        "mma.sync.aligned.m16n8k8.row.col.f32.tf32.tf32.f32 "
        "{%0,%1,%2,%3}, {%4,%5,%6,%7}, {%8,%9}, {%0,%1,%2,%3};\n"
        : "+f"(c[0]), "+f"(c[1]), "+f"(c[2]), "+f"(c[3])
        : "r"(a0), "r"(a1), "r"(a2), "r"(a3), "r"(b0), "r"(b1));
}

__device__ __forceinline__ void cp_async16(void* smem, const void* gmem) {
    uint32_t s = (uint32_t)__cvta_generic_to_shared(smem);
    asm volatile("cp.async.ca.shared.global [%0], [%1], 16;\n" :: "r"(s), "l"(gmem));
}
__device__ __forceinline__ void cp_commit() {
    asm volatile("cp.async.commit_group;\n");
}
__device__ __forceinline__ void cp_wait1() {
    asm volatile("cp.async.wait_group 1;\n");
}
__device__ __forceinline__ void cp_wait0() {
    asm volatile("cp.async.wait_group 0;\n");
}

// ---------------------------------------------------------------------------
// Fused projection GEMMs: one launch, blockIdx.z selects {Q, K, V}.
// CTA tile 128x128, BK=16, 256 threads (8 warps, 4x2), warp tile 32x64.
// 3-stage cp.async pipeline; dynamic smem (61.4 KB).
//  z=0: Q -> tf32 out, scaled 1/32     (1-pass tf32)
//  z=1: K -> tf32 out                  (1-pass tf32)
//  z=2: V -> transposed tf32 out       (2-pass: W-side exact split)
// ---------------------------------------------------------------------------
#define BM 128
#define BN 128
#define BK 16
#define KPAD 4
#define BKP (BK + KPAD)
#define NSTG 3
#define A_STG (BM * BKP)              // 2560 floats per stage
#define B_STG (BN * BKP)              // 2560 floats per stage
#define GEMM_SMEM (NSTG * (A_STG + B_STG) * (int)sizeof(float))   // 61440

__device__ __forceinline__ void gemm_load_stage(
    const float* __restrict__ X, const float* __restrict__ W,
    float* As, float* Bs, int m0, int n0, int k0, int K, int tid)
{
    // A: 128 rows x 16 k = 512 float4; 2 per thread
#pragma unroll
    for (int i = 0; i < 2; i++) {
        int f   = tid + i * 256;
        int row = f >> 2;
        int kq  = (f & 3) * 4;
        cp_async16(&As[row * BKP + kq], &X[(size_t)(m0 + row) * K + k0 + kq]);
    }
    // B: 128 rows x 16 k = 512 float4; 2 per thread
#pragma unroll
    for (int i = 0; i < 2; i++) {
        int f   = tid + i * 256;
        int row = f >> 2;
        int kq  = (f & 3) * 4;
        cp_async16(&Bs[row * BKP + kq], &W[(size_t)(n0 + row) * K + k0 + kq]);
    }
    cp_commit();
}

__global__ __launch_bounds__(256) void gemm_fused(
    const float* __restrict__ qx, const float* __restrict__ Wq, const float* __restrict__ bq,
    const float* __restrict__ kx, const float* __restrict__ Wk, const float* __restrict__ bk,
    const float* __restrict__ vx, const float* __restrict__ Wv, const float* __restrict__ bv,
    uint32_t* __restrict__ YQ, uint32_t* __restrict__ YK,
    uint32_t* __restrict__ VT)
{
    extern __shared__ float smf[];
    float* AsBase = smf;                    // [NSTG][BM][BKP]
    float* BsBase = smf + NSTG * A_STG;     // [NSTG][BN][BKP]

    const int mode = blockIdx.z;
    const float* X    = (mode == 0) ? qx : (mode == 1) ? kx : vx;
    const float* W    = (mode == 0) ? Wq : (mode == 1) ? Wk : Wv;
    const float* bias = (mode == 0) ? bq : (mode == 1) ? bk : bv;

    const int tid  = threadIdx.x;
    const int warp = tid >> 5;
    const int lane = tid & 31;
    const int wm = (warp >> 1) * 32;     // 0,32,64,96
    const int wn = (warp & 1) * 64;      // 0,64
    const int g  = lane >> 2;
    const int tg = lane & 3;
    const int m0 = blockIdx.y * BM;
    const int n0 = blockIdx.x * BN;
    const int K = DM, N = DM;
    const int NIT = K / BK;

    float c[2][8][4];
#pragma unroll
    for (int mt = 0; mt < 2; mt++)
#pragma unroll
        for (int nt = 0; nt < 8; nt++)
#pragma unroll
            for (int r = 0; r < 4; r++) c[mt][nt][r] = 0.0f;

    gemm_load_stage(X, W, AsBase, BsBase, m0, n0, 0, K, tid);
    gemm_load_stage(X, W, AsBase + A_STG, BsBase + B_STG, m0, n0, BK, K, tid);

    for (int it = 0; it < NIT; it++) {
        if (it + 2 < NIT) cp_wait1(); else cp_wait0();
        __syncthreads();
        if (it + 2 < NIT) {
            int st2 = (it + 2) % NSTG;
            gemm_load_stage(X, W, AsBase + st2 * A_STG, BsBase + st2 * B_STG,
                            m0, n0, (it + 2) * BK, K, tid);
        }

        const int st = it % NSTG;
        const float* As = AsBase + st * A_STG;
        const float* Bs = BsBase + st * B_STG;

        if (mode < 2) {
            // 1-pass tf32
#pragma unroll
            for (int ks = 0; ks < 2; ks++) {
                const int kb = ks * 8;
                uint32_t a[2][4];
#pragma unroll
                for (int mt = 0; mt < 2; mt++) {
                    int r0 = wm + mt * 16;
                    a[mt][0] = cvt_tf32(As[(r0 + g    ) * BKP + kb + tg    ]);
                    a[mt][1] = cvt_tf32(As[(r0 + g + 8) * BKP + kb + tg    ]);
                    a[mt][2] = cvt_tf32(As[(r0 + g    ) * BKP + kb + tg + 4]);
                    a[mt][3] = cvt_tf32(As[(r0 + g + 8) * BKP + kb + tg + 4]);
                }
#pragma unroll
                for (int nt = 0; nt < 8; nt++) {
                    int nr = wn + nt * 8 + g;
                    uint32_t b0 = cvt_tf32(Bs[nr * BKP + kb + tg    ]);
                    uint32_t b1 = cvt_tf32(Bs[nr * BKP + kb + tg + 4]);
#pragma unroll
                    for (int mt = 0; mt < 2; mt++)
                        mma_tf32(c[mt][nt], a[mt][0], a[mt][1], a[mt][2], a[mt][3], b0, b1);
                }
            }
        } else {
            // 2-pass: X single-cvt (A), W split (B) -> W-side exact
#pragma unroll
            for (int ks = 0; ks < 2; ks++) {
                const int kb = ks * 8;
                uint32_t a[2][4];
#pragma unroll
                for (int mt = 0; mt < 2; mt++) {
                    int r0 = wm + mt * 16;
                    a[mt][0] = cvt_tf32(As[(r0 + g    ) * BKP + kb + tg    ]);
                    a[mt][1] = cvt_tf32(As[(r0 + g + 8) * BKP + kb + tg    ]);
                    a[mt][2] = cvt_tf32(As[(r0 + g    ) * BKP + kb + tg + 4]);
                    a[mt][3] = cvt_tf32(As[(r0 + g + 8) * BKP + kb + tg + 4]);
                }
#pragma unroll
                for (int nt = 0; nt < 8; nt++) {
                    int nr = wn + nt * 8 + g;
                    uint32_t bh0, bl0, bh1, bl1;
                    tf32_split(Bs[nr * BKP + kb + tg    ], bh0, bl0);
                    tf32_split(Bs[nr * BKP + kb + tg + 4], bh1, bl1);
#pragma unroll
                    for (int mt = 0; mt < 2; mt++) {
                        mma_tf32(c[mt][nt], a[mt][0], a[mt][1], a[mt][2], a[mt][3], bh0, bh1);
                        mma_tf32(c[mt][nt], a[mt][0], a[mt][1], a[mt][2], a[mt][3], bl0, bl1);
                    }
                }
            }
        }
        __syncthreads();
    }

    if (mode < 2) {
        uint32_t* Y = (mode == 0) ? YQ : YK;
        const float oscale = (mode == 0) ? 0.03125f : 1.0f;
#pragma unroll
        for (int mt = 0; mt < 2; mt++) {
#pragma unroll
            for (int nt = 0; nt < 8; nt++) {
                int m = m0 + wm + mt * 16 + g;
                int n = n0 + wn + nt * 8 + tg * 2;
                float b0 = bias[n];
                float b1 = bias[n + 1];
                Y[(size_t)m * N + n]           = cvt_tf32((c[mt][nt][0] + b0) * oscale);
                Y[(size_t)m * N + n + 1]       = cvt_tf32((c[mt][nt][1] + b1) * oscale);
                Y[(size_t)(m + 8) * N + n]     = cvt_tf32((c[mt][nt][2] + b0) * oscale);
                Y[(size_t)(m + 8) * N + n + 1] = cvt_tf32((c[mt][nt][3] + b1) * oscale);
            }
        }
    } else {
        // Transposed epilogue: m=(b,s), n=(h,d) -> VT[((b*NH+h)*HDIM+d)*SS + s], tf32
#pragma unroll
        for (int mt = 0; mt < 2; mt++) {
#pragma unroll
            for (int nt = 0; nt < 8; nt++) {
                int m = m0 + wm + mt * 16 + g;
                int n = n0 + wn + nt * 8 + tg * 2;
                int bidx = m >> 11, s = m & 2047;
#pragma unroll
                for (int e = 0; e < 2; e++) {
                    int nn = n + e;
                    int hh = nn >> 6, dd = nn & 63;
                    size_t base = (((size_t)(bidx * NH + hh)) * HDIM + dd) * SS;
                    float bb = bias[nn];
                    VT[base + s]     = cvt_tf32(c[mt][nt][e]     + bb);
                    VT[base + s + 8] = cvt_tf32(c[mt][nt][e + 2] + bb);
                }
            }
        }
    }
}

// ---------------------------------------------------------------------------
// Tensor-core flash attention (TF32), causal. 128 threads, 4 warps x 32 q-rows.
// (byte-identical to the measured-best R14 kernel)
// ---------------------------------------------------------------------------
#define QT 128
#define KT 64
#define PSTR 68
#define FA_SMEM ((2 * 64 * PSTR + 4 * 32 * PSTR) * (int)sizeof(uint32_t))

__global__ __launch_bounds__(128) void flash_attn_tc(
    const uint32_t* __restrict__ Qt, const uint32_t* __restrict__ Kt,
    const uint32_t* __restrict__ VT, float* __restrict__ O)
{
    extern __shared__ uint32_t smu[];
    uint32_t* sK = smu;                  // K tile [64 keys][PSTR] (cols = d)
    uint32_t* sV = smu + 64 * PSTR;      // V^T tile [64 d][PSTR]  (cols = key)
    uint32_t* sP = smu + 2 * 64 * PSTR;  // per-warp P [32][PSTR]

    const int tid  = threadIdx.x;
    const int w    = tid >> 5;
    const int lane = tid & 31;
    const int g    = lane >> 2;
    const int tg   = lane & 3;
    const int qt   = (int)gridDim.x - 1 - (int)blockIdx.x;
    const int h    = blockIdx.y;
    const int b    = blockIdx.z;
    const int qbase = qt * QT;
    const float NEG = -1.0e30f;

    const uint32_t* Qg = Qt + ((size_t)(b * SS) + qbase) * DM + h * HDIM;
    uint32_t qf[2][8][4];
#pragma unroll
    for (int mt = 0; mt < 2; mt++) {
        int r0 = w * 32 + mt * 16 + g;
#pragma unroll
        for (int ks = 0; ks < 8; ks++) {
            int cc = ks * 8 + tg;
            qf[mt][ks][0] = Qg[(size_t)(r0    ) * DM + cc    ];
            qf[mt][ks][1] = Qg[(size_t)(r0 + 8) * DM + cc    ];
            qf[mt][ks][2] = Qg[(size_t)(r0    ) * DM + cc + 4];
            qf[mt][ks][3] = Qg[(size_t)(r0 + 8) * DM + cc + 4];
        }
    }

    float of[2][8][4];
    float mrow[2][2], lrow[2][2];
#pragma unroll
    for (int mt = 0; mt < 2; mt++) {
        mrow[mt][0] = NEG; mrow[mt][1] = NEG;
        lrow[mt][0] = 0.f; lrow[mt][1] = 0.f;
#pragma unroll
        for (int nt = 0; nt < 8; nt++)
#pragma unroll
            for (int r = 0; r < 4; r++) of[mt][nt][r] = 0.f;
    }

    uint32_t* Pw = sP + w * 32 * PSTR;
    const int nkt = 2 * qt + 2;

    for (int kt = 0; kt < nkt; kt++) {
        __syncthreads();
        const uint32_t* Kg = Kt + ((size_t)(b * SS) + kt * KT) * DM + h * HDIM;
        size_t vbase = ((size_t)(b * NH + h) * HDIM) * SS + kt * KT;
#pragma unroll
        for (int i = 0; i < 8; i++) {
            int f = tid + i * 128;
            int row = f >> 4, c4 = (f & 15) * 4;
            *(uint4*)&sK[row * PSTR + c4] = *(const uint4*)&Kg[(size_t)row * DM + c4];
            *(uint4*)&sV[row * PSTR + c4] = *(const uint4*)&VT[vbase + (size_t)row * SS + c4];
        }
        __syncthreads();

        if (kt * KT > qbase + w * 32 + 31) continue;

        float s[2][8][4];
#pragma unroll
        for (int mt = 0; mt < 2; mt++)
#pragma unroll
            for (int nt = 0; nt < 8; nt++)
#pragma unroll
                for (int r = 0; r < 4; r++) s[mt][nt][r] = 0.f;

#pragma unroll
        for (int ks = 0; ks < 8; ks++) {
#pragma unroll
            for (int nt = 0; nt < 8; nt++) {
                int nr = nt * 8 + g;
                uint32_t b0 = sK[nr * PSTR + ks * 8 + tg    ];
                uint32_t b1 = sK[nr * PSTR + ks * 8 + tg + 4];
                mma_tf32(s[0][nt], qf[0][ks][0], qf[0][ks][1], qf[0][ks][2], qf[0][ks][3], b0, b1);
                mma_tf32(s[1][nt], qf[1][ks][0], qf[1][ks][1], qf[1][ks][2], qf[1][ks][3], b0, b1);
            }
        }

        if (kt >= 2 * qt) {
#pragma unroll
            for (int mt = 0; mt < 2; mt++) {
                int row0 = qbase + w * 32 + mt * 16 + g;
#pragma unroll
                for (int nt = 0; nt < 8; nt++) {
                    int col = kt * KT + nt * 8 + 2 * tg;
                    if (col     > row0    ) s[mt][nt][0] = NEG;
                    if (col + 1 > row0    ) s[mt][nt][1] = NEG;
                    if (col     > row0 + 8) s[mt][nt][2] = NEG;
                    if (col + 1 > row0 + 8) s[mt][nt][3] = NEG;
                }
            }
        }

#pragma unroll
        for (int mt = 0; mt < 2; mt++) {
            float rm0 = NEG, rm1 = NEG;
#pragma unroll
            for (int nt = 0; nt < 8; nt++) {
                rm0 = fmaxf(rm0, fmaxf(s[mt][nt][0], s[mt][nt][1]));
                rm1 = fmaxf(rm1, fmaxf(s[mt][nt][2], s[mt][nt][3]));
            }
#pragma unroll
            for (int d = 1; d < 4; d <<= 1) {
                rm0 = fmaxf(rm0, __shfl_xor_sync(0xffffffffu, rm0, d));
                rm1 = fmaxf(rm1, __shfl_xor_sync(0xffffffffu, rm1, d));
            }
            float mn0 = fmaxf(mrow[mt][0], rm0);
            float mn1 = fmaxf(mrow[mt][1], rm1);
            float corr0 = __expf(mrow[mt][0] - mn0);
            float corr1 = __expf(mrow[mt][1] - mn1);
            float rs0 = 0.f, rs1 = 0.f;
#pragma unroll
            for (int nt = 0; nt < 8; nt++) {
                s[mt][nt][0] = __expf(s[mt][nt][0] - mn0);
                s[mt][nt][1] = __expf(s[mt][nt][1] - mn0);
                s[mt][nt][2] = __expf(s[mt][nt][2] - mn1);
                s[mt][nt][3] = __expf(s[mt][nt][3] - mn1);
                rs0 += s[mt][nt][0] + s[mt][nt][1];
                rs1 += s[mt][nt][2] + s[mt][nt][3];
            }
#pragma unroll
            for (int d = 1; d < 4; d <<= 1) {
                rs0 += __shfl_xor_sync(0xffffffffu, rs0, d);
                rs1 += __shfl_xor_sync(0xffffffffu, rs1, d);
            }
            lrow[mt][0] = lrow[mt][0] * corr0 + rs0;
            lrow[mt][1] = lrow[mt][1] * corr1 + rs1;
            mrow[mt][0] = mn0;
            mrow[mt][1] = mn1;
#pragma unroll
            for (int nt = 0; nt < 8; nt++) {
                of[mt][nt][0] *= corr0;
                of[mt][nt][1] *= corr0;
                of[mt][nt][2] *= corr1;
                of[mt][nt][3] *= corr1;
            }
            int pr = mt * 16 + g;
#pragma unroll
            for (int nt = 0; nt < 8; nt++) {
                uint2 p01 = make_uint2(cvt_tf32(s[mt][nt][0]), cvt_tf32(s[mt][nt][1]));
                uint2 p23 = make_uint2(cvt_tf32(s[mt][nt][2]), cvt_tf32(s[mt][nt][3]));
                *(uint2*)&Pw[(pr    ) * PSTR + nt * 8 + 2 * tg] = p01;
                *(uint2*)&Pw[(pr + 8) * PSTR + nt * 8 + 2 * tg] = p23;
            }
        }
        __syncwarp();

        // O += P V (single-pass tf32)
#pragma unroll
        for (int ks = 0; ks < 8; ks++) {
            uint32_t a[2][4];
#pragma unroll
            for (int mt = 0; mt < 2; mt++) {
                int pr = mt * 16 + g;
                int cc = ks * 8 + tg;
                a[mt][0] = Pw[(pr    ) * PSTR + cc    ];
                a[mt][1] = Pw[(pr + 8) * PSTR + cc    ];
                a[mt][2] = Pw[(pr    ) * PSTR + cc + 4];
                a[mt][3] = Pw[(pr + 8) * PSTR + cc + 4];
            }
#pragma unroll
            for (int nt = 0; nt < 8; nt++) {
                int nr = nt * 8 + g;
                uint32_t b0 = sV[nr * PSTR + ks * 8 + tg    ];
                uint32_t b1 = sV[nr * PSTR + ks * 8 + tg + 4];
#pragma unroll
                for (int mt = 0; mt < 2; mt++)
                    mma_tf32(of[mt][nt], a[mt][0], a[mt][1], a[mt][2], a[mt][3], b0, b1);
            }
        }
        __syncwarp();
    }

    float* Og = O + ((size_t)(b * SS) + qbase) * DM + h * HDIM;
#pragma unroll
    for (int mt = 0; mt < 2; mt++) {
        float inv0 = 1.0f / lrow[mt][0];
        float inv1 = 1.0f / lrow[mt][1];
        int r0 = w * 32 + mt * 16 + g;
#pragma unroll
        for (int nt = 0; nt < 8; nt++) {
            int cc = nt * 8 + 2 * tg;
            *(float2*)&Og[(size_t)(r0    ) * DM + cc] =
                make_float2(of[mt][nt][0] * inv0, of[mt][nt][1] * inv0);
            *(float2*)&Og[(size_t)(r0 + 8) * DM + cc] =
                make_float2(of[mt][nt][2] * inv1, of[mt][nt][3] * inv1);
        }
    }
}

// ---------------------------------------------------------------------------
// kernel_launch
// ---------------------------------------------------------------------------
extern "C" void kernel_launch(void* const* d_in, const int* in_sizes, int n_in,
                              void* d_out, int out_size)
{
    const float* qx = (const float*)d_in[0];
    const float* kx = (const float*)d_in[1];
    const float* vx = (const float*)d_in[2];
    const float* Wq = (const float*)d_in[4];
    const float* bq = (const float*)d_in[5];
    const float* Wk = (const float*)d_in[6];
    const float* bk = (const float*)d_in[7];
    const float* Wv = (const float*)d_in[8];
    const float* bv = (const float*)d_in[9];
    float* out = (float*)d_out;

    uint32_t *gq, *gk, *gv;
    cudaGetSymbolAddress((void**)&gq, g_qt);
    cudaGetSymbolAddress((void**)&gk, g_kt);
    cudaGetSymbolAddress((void**)&gv, g_vt);

    cudaFuncSetAttribute(gemm_fused,
                         cudaFuncAttributeMaxDynamicSharedMemorySize, GEMM_SMEM);
    dim3 ggrid(DM / BN, (BB * SS) / BM, 3);   // (8, 32, 3)
    gemm_fused<<<ggrid, 256, GEMM_SMEM>>>(qx, Wq, bq, kx, Wk, bk, vx, Wv, bv,
                                          gq, gk, gv);

    cudaFuncSetAttribute(flash_attn_tc,
                         cudaFuncAttributeMaxDynamicSharedMemorySize, FA_SMEM);
    dim3 agrid(SS / QT, NH, BB);    // (16, 16, 2)
    flash_attn_tc<<<agrid, 128, FA_SMEM>>>(gq, gk, gv, out);
}

// round 17
// speedup vs baseline: 1.3691x; 1.0079x over previous
#include <cuda_runtime.h>
#include <math.h>
#include <stdint.h>

// Problem constants
#define BB   2
#define SS   2048
#define DM   1024
#define NH   16
#define HDIM 64

// Scratch (device globals: allocation-free)
__device__ uint32_t g_qt[BB * SS * DM];
__device__ uint32_t g_kt[BB * SS * DM];
__device__ uint32_t g_vt[BB * NH * HDIM * SS];   // V^T as single tf32 plane

// ---------------------------------------------------------------------------
// Helpers
// ---------------------------------------------------------------------------
__device__ __forceinline__ void tf32_split(float x, uint32_t& hi, uint32_t& lo) {
    uint32_t xh = __float_as_uint(x) & 0xFFFFE000u;
    hi = xh;
    lo = __float_as_uint(x - __uint_as_float(xh));
}

__device__ __forceinline__ uint32_t cvt_tf32(float x) {
    uint32_t u;
    asm("cvt.rna.tf32.f32 %0, %1;" : "=r"(u) : "f"(x));
    return u;
}

__device__ __forceinline__ void mma_tf32(float* c,
                                         uint32_t a0, uint32_t a1, uint32_t a2, uint32_t a3,
                                         uint32_t b0, uint32_t b1) {
    asm volatile(
        "mma.sync.aligned.m16n8k8.row.col.f32.tf32.tf32.f32 "
        "{%0,%1,%2,%3}, {%4,%5,%6,%7}, {%8,%9}, {%0,%1,%2,%3};\n"
        : "+f"(c[0]), "+f"(c[1]), "+f"(c[2]), "+f"(c[3])
        : "r"(a0), "r"(a1), "r"(a2), "r"(a3), "r"(b0), "r"(b1));
}

__device__ __forceinline__ void cp_async16(void* smem, const void* gmem) {
    uint32_t s = (uint32_t)__cvta_generic_to_shared(smem);
    asm volatile("cp.async.ca.shared.global [%0], [%1], 16;\n" :: "r"(s), "l"(gmem));
}
__device__ __forceinline__ void cp_commit() {
    asm volatile("cp.async.commit_group;\n");
}
__device__ __forceinline__ void cp_wait0() {
    asm volatile("cp.async.wait_group 0;\n");
}

// ---------------------------------------------------------------------------
// Fused projection GEMMs: one launch, blockIdx.z selects {Q, K, V}.
// CTA tile 128x128, BK=32, 256 threads (8 warps, 4x2), warp tile 32x64.
// Double-buffered cp.async pipeline; dynamic smem (73.7 KB).
//  z=0: Q -> tf32 out, scaled 1/32     (1-pass tf32)
//  z=1: K -> tf32 out                  (1-pass tf32)
//  z=2: V -> transposed tf32 out       (2-pass: W-side exact split)
// ---------------------------------------------------------------------------
#define BM 128
#define BN 128
#define BK 32
#define KPAD 4
#define BKP (BK + KPAD)
#define NSTG 2
#define A_STG (BM * BKP)              // 4608 floats per stage
#define B_STG (BN * BKP)              // 4608 floats per stage
#define GEMM_SMEM (NSTG * (A_STG + B_STG) * (int)sizeof(float))   // 73728

__device__ __forceinline__ void gemm_load_stage(
    const float* __restrict__ X, const float* __restrict__ W,
    float* As, float* Bs, int m0, int n0, int k0, int K, int tid)
{
    // A: 128 rows x 32 k = 1024 float4; 4 per thread
#pragma unroll
    for (int i = 0; i < 4; i++) {
        int f   = tid + i * 256;
        int row = f >> 3;
        int kq  = (f & 7) * 4;
        cp_async16(&As[row * BKP + kq], &X[(size_t)(m0 + row) * K + k0 + kq]);
    }
    // B: 128 rows x 32 k = 1024 float4; 4 per thread
#pragma unroll
    for (int i = 0; i < 4; i++) {
        int f   = tid + i * 256;
        int row = f >> 3;
        int kq  = (f & 7) * 4;
        cp_async16(&Bs[row * BKP + kq], &W[(size_t)(n0 + row) * K + k0 + kq]);
    }
    cp_commit();
}

__global__ __launch_bounds__(256) void gemm_fused(
    const float* __restrict__ qx, const float* __restrict__ Wq, const float* __restrict__ bq,
    const float* __restrict__ kx, const float* __restrict__ Wk, const float* __restrict__ bk,
    const float* __restrict__ vx, const float* __restrict__ Wv, const float* __restrict__ bv,
    uint32_t* __restrict__ YQ, uint32_t* __restrict__ YK,
    uint32_t* __restrict__ VT)
{
    extern __shared__ float smf[];
    float* AsBase = smf;                    // [NSTG][BM][BKP]
    float* BsBase = smf + NSTG * A_STG;     // [NSTG][BN][BKP]

    const int mode = blockIdx.z;
    const float* X    = (mode == 0) ? qx : (mode == 1) ? kx : vx;
    const float* W    = (mode == 0) ? Wq : (mode == 1) ? Wk : Wv;
    const float* bias = (mode == 0) ? bq : (mode == 1) ? bk : bv;

    const int tid  = threadIdx.x;
    const int warp = tid >> 5;
    const int lane = tid & 31;
    const int wm = (warp >> 1) * 32;     // 0,32,64,96
    const int wn = (warp & 1) * 64;      // 0,64
    const int g  = lane >> 2;
    const int tg = lane & 3;
    const int m0 = blockIdx.y * BM;
    const int n0 = blockIdx.x * BN;
    const int K = DM, N = DM;
    const int NIT = K / BK;              // 32

    float c[2][8][4];
#pragma unroll
    for (int mt = 0; mt < 2; mt++)
#pragma unroll
        for (int nt = 0; nt < 8; nt++)
#pragma unroll
            for (int r = 0; r < 4; r++) c[mt][nt][r] = 0.0f;

    gemm_load_stage(X, W, AsBase, BsBase, m0, n0, 0, K, tid);

    for (int it = 0; it < NIT; it++) {
        cp_wait0();
        __syncthreads();
        if (it + 1 < NIT) {
            int st2 = (it + 1) & 1;
            gemm_load_stage(X, W, AsBase + st2 * A_STG, BsBase + st2 * B_STG,
                            m0, n0, (it + 1) * BK, K, tid);
        }

        const int st = it & 1;
        const float* As = AsBase + st * A_STG;
        const float* Bs = BsBase + st * B_STG;

        if (mode < 2) {
            // 1-pass tf32
#pragma unroll
            for (int ks = 0; ks < 4; ks++) {
                const int kb = ks * 8;
                uint32_t a[2][4];
#pragma unroll
                for (int mt = 0; mt < 2; mt++) {
                    int r0 = wm + mt * 16;
                    a[mt][0] = cvt_tf32(As[(r0 + g    ) * BKP + kb + tg    ]);
                    a[mt][1] = cvt_tf32(As[(r0 + g + 8) * BKP + kb + tg    ]);
                    a[mt][2] = cvt_tf32(As[(r0 + g    ) * BKP + kb + tg + 4]);
                    a[mt][3] = cvt_tf32(As[(r0 + g + 8) * BKP + kb + tg + 4]);
                }
#pragma unroll
                for (int nt = 0; nt < 8; nt++) {
                    int nr = wn + nt * 8 + g;
                    uint32_t b0 = cvt_tf32(Bs[nr * BKP + kb + tg    ]);
                    uint32_t b1 = cvt_tf32(Bs[nr * BKP + kb + tg + 4]);
#pragma unroll
                    for (int mt = 0; mt < 2; mt++)
                        mma_tf32(c[mt][nt], a[mt][0], a[mt][1], a[mt][2], a[mt][3], b0, b1);
                }
            }
        } else {
            // 2-pass: X single-cvt (A), W split (B) -> W-side exact
#pragma unroll
            for (int ks = 0; ks < 4; ks++) {
                const int kb = ks * 8;
                uint32_t a[2][4];
#pragma unroll
                for (int mt = 0; mt < 2; mt++) {
                    int r0 = wm + mt * 16;
                    a[mt][0] = cvt_tf32(As[(r0 + g    ) * BKP + kb + tg    ]);
                    a[mt][1] = cvt_tf32(As[(r0 + g + 8) * BKP + kb + tg    ]);
                    a[mt][2] = cvt_tf32(As[(r0 + g    ) * BKP + kb + tg + 4]);
                    a[mt][3] = cvt_tf32(As[(r0 + g + 8) * BKP + kb + tg + 4]);
                }
#pragma unroll
                for (int nt = 0; nt < 8; nt++) {
                    int nr = wn + nt * 8 + g;
                    uint32_t bh0, bl0, bh1, bl1;
                    tf32_split(Bs[nr * BKP + kb + tg    ], bh0, bl0);
                    tf32_split(Bs[nr * BKP + kb + tg + 4], bh1, bl1);
#pragma unroll
                    for (int mt = 0; mt < 2; mt++) {
                        mma_tf32(c[mt][nt], a[mt][0], a[mt][1], a[mt][2], a[mt][3], bh0, bh1);
                        mma_tf32(c[mt][nt], a[mt][0], a[mt][1], a[mt][2], a[mt][3], bl0, bl1);
                    }
                }
            }
        }
        __syncthreads();
    }

    if (mode < 2) {
        uint32_t* Y = (mode == 0) ? YQ : YK;
        const float oscale = (mode == 0) ? 0.03125f : 1.0f;
#pragma unroll
        for (int mt = 0; mt < 2; mt++) {
#pragma unroll
            for (int nt = 0; nt < 8; nt++) {
                int m = m0 + wm + mt * 16 + g;
                int n = n0 + wn + nt * 8 + tg * 2;
                float b0 = bias[n];
                float b1 = bias[n + 1];
                Y[(size_t)m * N + n]           = cvt_tf32((c[mt][nt][0] + b0) * oscale);
                Y[(size_t)m * N + n + 1]       = cvt_tf32((c[mt][nt][1] + b1) * oscale);
                Y[(size_t)(m + 8) * N + n]     = cvt_tf32((c[mt][nt][2] + b0) * oscale);
                Y[(size_t)(m + 8) * N + n + 1] = cvt_tf32((c[mt][nt][3] + b1) * oscale);
            }
        }
    } else {
        // Transposed epilogue: m=(b,s), n=(h,d) -> VT[((b*NH+h)*HDIM+d)*SS + s], tf32
#pragma unroll
        for (int mt = 0; mt < 2; mt++) {
#pragma unroll
            for (int nt = 0; nt < 8; nt++) {
                int m = m0 + wm + mt * 16 + g;
                int n = n0 + wn + nt * 8 + tg * 2;
                int bidx = m >> 11, s = m & 2047;
#pragma unroll
                for (int e = 0; e < 2; e++) {
                    int nn = n + e;
                    int hh = nn >> 6, dd = nn & 63;
                    size_t base = (((size_t)(bidx * NH + hh)) * HDIM + dd) * SS;
                    float bb = bias[nn];
                    VT[base + s]     = cvt_tf32(c[mt][nt][e]     + bb);
                    VT[base + s + 8] = cvt_tf32(c[mt][nt][e + 2] + bb);
                }
            }
        }
    }
}

// ---------------------------------------------------------------------------
// Tensor-core flash attention (TF32), causal. 128 threads, 4 warps x 32 q-rows.
// (byte-identical to the measured-best R14/R16 kernel)
// ---------------------------------------------------------------------------
#define QT 128
#define KT 64
#define PSTR 68
#define FA_SMEM ((2 * 64 * PSTR + 4 * 32 * PSTR) * (int)sizeof(uint32_t))

__global__ __launch_bounds__(128) void flash_attn_tc(
    const uint32_t* __restrict__ Qt, const uint32_t* __restrict__ Kt,
    const uint32_t* __restrict__ VT, float* __restrict__ O)
{
    extern __shared__ uint32_t smu[];
    uint32_t* sK = smu;                  // K tile [64 keys][PSTR] (cols = d)
    uint32_t* sV = smu + 64 * PSTR;      // V^T tile [64 d][PSTR]  (cols = key)
    uint32_t* sP = smu + 2 * 64 * PSTR;  // per-warp P [32][PSTR]

    const int tid  = threadIdx.x;
    const int w    = tid >> 5;
    const int lane = tid & 31;
    const int g    = lane >> 2;
    const int tg   = lane & 3;
    const int qt   = (int)gridDim.x - 1 - (int)blockIdx.x;
    const int h    = blockIdx.y;
    const int b    = blockIdx.z;
    const int qbase = qt * QT;
    const float NEG = -1.0e30f;

    const uint32_t* Qg = Qt + ((size_t)(b * SS) + qbase) * DM + h * HDIM;
    uint32_t qf[2][8][4];
#pragma unroll
    for (int mt = 0; mt < 2; mt++) {
        int r0 = w * 32 + mt * 16 + g;
#pragma unroll
        for (int ks = 0; ks < 8; ks++) {
            int cc = ks * 8 + tg;
            qf[mt][ks][0] = Qg[(size_t)(r0    ) * DM + cc    ];
            qf[mt][ks][1] = Qg[(size_t)(r0 + 8) * DM + cc    ];
            qf[mt][ks][2] = Qg[(size_t)(r0    ) * DM + cc + 4];
            qf[mt][ks][3] = Qg[(size_t)(r0 + 8) * DM + cc + 4];
        }
    }

    float of[2][8][4];
    float mrow[2][2], lrow[2][2];
#pragma unroll
    for (int mt = 0; mt < 2; mt++) {
        mrow[mt][0] = NEG; mrow[mt][1] = NEG;
        lrow[mt][0] = 0.f; lrow[mt][1] = 0.f;
#pragma unroll
        for (int nt = 0; nt < 8; nt++)
#pragma unroll
            for (int r = 0; r < 4; r++) of[mt][nt][r] = 0.f;
    }

    uint32_t* Pw = sP + w * 32 * PSTR;
    const int nkt = 2 * qt + 2;

    for (int kt = 0; kt < nkt; kt++) {
        __syncthreads();
        const uint32_t* Kg = Kt + ((size_t)(b * SS) + kt * KT) * DM + h * HDIM;
        size_t vbase = ((size_t)(b * NH + h) * HDIM) * SS + kt * KT;
#pragma unroll
        for (int i = 0; i < 8; i++) {
            int f = tid + i * 128;
            int row = f >> 4, c4 = (f & 15) * 4;
            *(uint4*)&sK[row * PSTR + c4] = *(const uint4*)&Kg[(size_t)row * DM + c4];
            *(uint4*)&sV[row * PSTR + c4] = *(const uint4*)&VT[vbase + (size_t)row * SS + c4];
        }
        __syncthreads();

        if (kt * KT > qbase + w * 32 + 31) continue;

        float s[2][8][4];
#pragma unroll
        for (int mt = 0; mt < 2; mt++)
#pragma unroll
            for (int nt = 0; nt < 8; nt++)
#pragma unroll
                for (int r = 0; r < 4; r++) s[mt][nt][r] = 0.f;

#pragma unroll
        for (int ks = 0; ks < 8; ks++) {
#pragma unroll
            for (int nt = 0; nt < 8; nt++) {
                int nr = nt * 8 + g;
                uint32_t b0 = sK[nr * PSTR + ks * 8 + tg    ];
                uint32_t b1 = sK[nr * PSTR + ks * 8 + tg + 4];
                mma_tf32(s[0][nt], qf[0][ks][0], qf[0][ks][1], qf[0][ks][2], qf[0][ks][3], b0, b1);
                mma_tf32(s[1][nt], qf[1][ks][0], qf[1][ks][1], qf[1][ks][2], qf[1][ks][3], b0, b1);
            }
        }

        if (kt >= 2 * qt) {
#pragma unroll
            for (int mt = 0; mt < 2; mt++) {
                int row0 = qbase + w * 32 + mt * 16 + g;
#pragma unroll
                for (int nt = 0; nt < 8; nt++) {
                    int col = kt * KT + nt * 8 + 2 * tg;
                    if (col     > row0    ) s[mt][nt][0] = NEG;
                    if (col + 1 > row0    ) s[mt][nt][1] = NEG;
                    if (col     > row0 + 8) s[mt][nt][2] = NEG;
                    if (col + 1 > row0 + 8) s[mt][nt][3] = NEG;
                }
            }
        }

#pragma unroll
        for (int mt = 0; mt < 2; mt++) {
            float rm0 = NEG, rm1 = NEG;
#pragma unroll
            for (int nt = 0; nt < 8; nt++) {
                rm0 = fmaxf(rm0, fmaxf(s[mt][nt][0], s[mt][nt][1]));
                rm1 = fmaxf(rm1, fmaxf(s[mt][nt][2], s[mt][nt][3]));
            }
#pragma unroll
            for (int d = 1; d < 4; d <<= 1) {
                rm0 = fmaxf(rm0, __shfl_xor_sync(0xffffffffu, rm0, d));
                rm1 = fmaxf(rm1, __shfl_xor_sync(0xffffffffu, rm1, d));
            }
            float mn0 = fmaxf(mrow[mt][0], rm0);
            float mn1 = fmaxf(mrow[mt][1], rm1);
            float corr0 = __expf(mrow[mt][0] - mn0);
            float corr1 = __expf(mrow[mt][1] - mn1);
            float rs0 = 0.f, rs1 = 0.f;
#pragma unroll
            for (int nt = 0; nt < 8; nt++) {
                s[mt][nt][0] = __expf(s[mt][nt][0] - mn0);
                s[mt][nt][1] = __expf(s[mt][nt][1] - mn0);
                s[mt][nt][2] = __expf(s[mt][nt][2] - mn1);
                s[mt][nt][3] = __expf(s[mt][nt][3] - mn1);
                rs0 += s[mt][nt][0] + s[mt][nt][1];
                rs1 += s[mt][nt][2] + s[mt][nt][3];
            }
#pragma unroll
            for (int d = 1; d < 4; d <<= 1) {
                rs0 += __shfl_xor_sync(0xffffffffu, rs0, d);
                rs1 += __shfl_xor_sync(0xffffffffu, rs1, d);
            }
            lrow[mt][0] = lrow[mt][0] * corr0 + rs0;
            lrow[mt][1] = lrow[mt][1] * corr1 + rs1;
            mrow[mt][0] = mn0;
            mrow[mt][1] = mn1;
#pragma unroll
            for (int nt = 0; nt < 8; nt++) {
                of[mt][nt][0] *= corr0;
                of[mt][nt][1] *= corr0;
                of[mt][nt][2] *= corr1;
                of[mt][nt][3] *= corr1;
            }
            int pr = mt * 16 + g;
#pragma unroll
            for (int nt = 0; nt < 8; nt++) {
                uint2 p01 = make_uint2(cvt_tf32(s[mt][nt][0]), cvt_tf32(s[mt][nt][1]));
                uint2 p23 = make_uint2(cvt_tf32(s[mt][nt][2]), cvt_tf32(s[mt][nt][3]));
                *(uint2*)&Pw[(pr    ) * PSTR + nt * 8 + 2 * tg] = p01;
                *(uint2*)&Pw[(pr + 8) * PSTR + nt * 8 + 2 * tg] = p23;
            }
        }
        __syncwarp();

        // O += P V (single-pass tf32)
#pragma unroll
        for (int ks = 0; ks < 8; ks++) {
            uint32_t a[2][4];
#pragma unroll
            for (int mt = 0; mt < 2; mt++) {
                int pr = mt * 16 + g;
                int cc = ks * 8 + tg;
                a[mt][0] = Pw[(pr    ) * PSTR + cc    ];
                a[mt][1] = Pw[(pr + 8) * PSTR + cc    ];
                a[mt][2] = Pw[(pr    ) * PSTR + cc + 4];
                a[mt][3] = Pw[(pr + 8) * PSTR + cc + 4];
            }
#pragma unroll
            for (int nt = 0; nt < 8; nt++) {
                int nr = nt * 8 + g;
                uint32_t b0 = sV[nr * PSTR + ks * 8 + tg    ];
                uint32_t b1 = sV[nr * PSTR + ks * 8 + tg + 4];
#pragma unroll
                for (int mt = 0; mt < 2; mt++)
                    mma_tf32(of[mt][nt], a[mt][0], a[mt][1], a[mt][2], a[mt][3], b0, b1);
            }
        }
        __syncwarp();
    }

    float* Og = O + ((size_t)(b * SS) + qbase) * DM + h * HDIM;
#pragma unroll
    for (int mt = 0; mt < 2; mt++) {
        float inv0 = 1.0f / lrow[mt][0];
        float inv1 = 1.0f / lrow[mt][1];
        int r0 = w * 32 + mt * 16 + g;
#pragma unroll
        for (int nt = 0; nt < 8; nt++) {
            int cc = nt * 8 + 2 * tg;
            *(float2*)&Og[(size_t)(r0    ) * DM + cc] =
                make_float2(of[mt][nt][0] * inv0, of[mt][nt][1] * inv0);
            *(float2*)&Og[(size_t)(r0 + 8) * DM + cc] =
                make_float2(of[mt][nt][2] * inv1, of[mt][nt][3] * inv1);
        }
    }
}

// ---------------------------------------------------------------------------
// kernel_launch
// ---------------------------------------------------------------------------
extern "C" void kernel_launch(void* const* d_in, const int* in_sizes, int n_in,
                              void* d_out, int out_size)
{
    const float* qx = (const float*)d_in[0];
    const float* kx = (const float*)d_in[1];
    const float* vx = (const float*)d_in[2];
    const float* Wq = (const float*)d_in[4];
    const float* bq = (const float*)d_in[5];
    const float* Wk = (const float*)d_in[6];
    const float* bk = (const float*)d_in[7];
    const float* Wv = (const float*)d_in[8];
    const float* bv = (const float*)d_in[9];
    float* out = (float*)d_out;

    uint32_t *gq, *gk, *gv;
    cudaGetSymbolAddress((void**)&gq, g_qt);
    cudaGetSymbolAddress((void**)&gk, g_kt);
    cudaGetSymbolAddress((void**)&gv, g_vt);

    cudaFuncSetAttribute(gemm_fused,
                         cudaFuncAttributeMaxDynamicSharedMemorySize, GEMM_SMEM);
    dim3 ggrid(DM / BN, (BB * SS) / BM, 3);   // (8, 32, 3)
    gemm_fused<<<ggrid, 256, GEMM_SMEM>>>(qx, Wq, bq, kx, Wk, bk, vx, Wv, bv,
                                          gq, gk, gv);

    cudaFuncSetAttribute(flash_attn_tc,
                         cudaFuncAttributeMaxDynamicSharedMemorySize, FA_SMEM);
    dim3 agrid(SS / QT, NH, BB);    // (16, 16, 2)
    flash_attn_tc<<<agrid, 128, FA_SMEM>>>(gq, gk, gv, out);
}